// round 9
// baseline (speedup 1.0000x reference)
#include <cuda_runtime.h>

#define N_NODES 100000
#define N_EDGES 1600000
#define HMW 32            // concatenated mu(16) | logstd(16)
#define OUTC 16

// ---------------- scratch (device globals; no allocations allowed) -------------
__device__ float g_deg  [N_NODES];         // in-degree count (dst)
__device__ float g_acc0 [N_NODES * 2];     // layer-1 aggregation of dis*x
__device__ float g_gvec [N_NODES * HMW];   // g = dis * (h @ [Wmu|Wls])
__device__ float g_acc1 [N_NODES * HMW];   // layer-2 accumulator (init = gvec)
__device__ int   g_src32[N_EDGES];         // compacted int32 src
__device__ int   g_dst32[N_EDGES];         // compacted int32 dst
__device__ int   g_is64;                   // edge_index dtype flag

// ---------------- vectorized L2 reductions (sm_90+) -----------------------------
__device__ __forceinline__ void red_add_v4(float* addr, float4 v) {
    asm volatile("red.global.add.v4.f32 [%0], {%1, %2, %3, %4};"
                 :: "l"(addr), "f"(v.x), "f"(v.y), "f"(v.z), "f"(v.w) : "memory");
}
__device__ __forceinline__ void red_add_v2(float* addr, float a, float b) {
    asm volatile("red.global.add.v2.f32 [%0], {%1, %2};"
                 :: "l"(addr), "f"(a), "f"(b) : "memory");
}

// ---------------- packed f32x2 helpers (sm_100+; FFMA2 in SASS) ------------------
#define FMA_F32X2(acc, a, b) \
    asm("fma.rn.f32x2 %0, %1, %2, %0;" : "+l"(acc) : "l"(a), "l"(b))
#define PACK2(out, s) \
    asm("mov.b64 %0, {%1, %1};" : "=l"(out) : "f"(s))
#define UNPACK2(lo, hi, in) \
    asm("mov.b64 {%0, %1}, %2;" : "=f"(lo), "=f"(hi) : "l"(in))

// ---------------- init: block 0 detects dtype; all blocks zero deg + acc0 -------
// int64 indices < 100000 have all-zero high words -> OR over 4096 words detects.
__global__ void k_init(const unsigned* ei_words) {
    if (blockIdx.x == 0) {
        __shared__ unsigned s_or[256];
        unsigned v = 0;
        for (int i = threadIdx.x; i < 4096; i += 256)
            v |= ei_words[2 * i + 1];
        s_or[threadIdx.x] = v;
        __syncthreads();
        for (int s = 128; s > 0; s >>= 1) {
            if (threadIdx.x < s) s_or[threadIdx.x] |= s_or[threadIdx.x + s];
            __syncthreads();
        }
        if (threadIdx.x == 0) g_is64 = (s_or[0] == 0u) ? 1 : 0;
    }
    const float4 z = make_float4(0.f, 0.f, 0.f, 0.f);
    int i = blockIdx.x * 256 + threadIdx.x;
    if (i < N_NODES * 2 / 4) ((float4*)g_acc0)[i] = z;   // 50000 float4
    if (i < N_NODES / 4)     ((float4*)g_deg )[i] = z;   // 25000 float4
}

// ---------------- degree + edge compaction to int32 -----------------------------
__global__ void k_deg(const void* ei) {
    int e = blockIdx.x * 256 + threadIdx.x;
    if (e >= N_EDGES) return;
    int src, dst;
    if (g_is64) {
        const long long* p = (const long long*)ei;
        src = (int)p[e];
        dst = (int)p[N_EDGES + e];
    } else {
        const int* p = (const int*)ei;
        src = p[e];
        dst = p[N_EDGES + e];
    }
    g_src32[e] = src;
    g_dst32[e] = dst;
    atomicAdd(&g_deg[dst], 1.0f);
}

// ---------------- layer-1 scatter: acc0[dst] += dis[src] * x[src]  (2 feats) ----
__global__ void k_scatter0(const float* __restrict__ x) {
    int e = blockIdx.x * 256 + threadIdx.x;
    if (e >= N_EDGES) return;
    int src = g_src32[e];
    int dst = g_dst32[e];
    float ds = rsqrtf(1.0f + g_deg[src]);
    float2 xv = ((const float2*)x)[src];
    red_add_v2(&g_acc0[2 * dst], ds * xv.x, ds * xv.y);
}

// ---------------- dense: h = relu(aggX @ W1 + b1); g = dis * (h @ [Wmu|Wls]) ----
// 4 threads/node (8 outputs each) x 4 nodes/thread, packed f32x2 accumulators:
// each k-iter per node = 4 FFMA2 + hk(2 FFMA + FMNMX + 1 pack) = 8 issue slots
// for 8 outputs (was 11 scalar). Weights read from shared as ulonglong2 so the
// f32x2 operands come straight out of LDS.128 register pairs.
// Seeds acc1 with the self-loop term (= gvec), replacing the zeroing pass.
__global__ void __launch_bounds__(256) k_hidden(
        const float* __restrict__ x, const float* __restrict__ W1,
        const float* __restrict__ b1,
        const float* __restrict__ Wmu, const float* __restrict__ Wls) {
    __shared__ ulonglong2 sW2[64][4];   // [k][part]: 4 floats = 2 f32x2, 4KB
    __shared__ float4 sWb[64];          // (W1[0][k], W1[1][k], b1[k], 0)

    int t = threadIdx.x;
    for (int i = t; i < 512; i += 256) {
        int k = i >> 3, q = i & 7;      // q indexes 8 float4s per k (32 floats)
        float4 v = (q < 4) ? ((const float4*)Wmu)[k * 4 + q]
                           : ((const float4*)Wls)[k * 4 + (q - 4)];
        ((float4*)&sW2[k][0])[q] = v;   // wait: sW2[k] is 4x16B=64B, q in 0..7 overflows
    }
    // NOTE: sW2 must hold 32 floats per k = 128B = 8 ulonglong2; fix layout below.
    __syncthreads();
    // (layout handled by sW2 being declared [64][4] of ulonglong2 = 64B -- WRONG)
    // -- see corrected declaration below --
    // This placeholder is replaced; real code uses sW2b.
    __syncthreads();

    // ---- real implementation ----
    // fallthrough never executes; actual kernel body is in k_hidden_impl style
    // (kept single-kernel: see below)
    (void)x; (void)W1; (void)b1;
}

// Corrected single k_hidden (the one actually launched):
__global__ void __launch_bounds__(256) k_hidden2(
        const float* __restrict__ x, const float* __restrict__ W1,
        const float* __restrict__ b1,
        const float* __restrict__ Wmu, const float* __restrict__ Wls) {
    __shared__ ulonglong2 sW2[64][8];   // [k][j/4]: each = 4 floats (2 f32x2), 8KB
    __shared__ float4 sWb[64];          // (W1[0][k], W1[1][k], b1[k], 0)

    int t = threadIdx.x;
    for (int i = t; i < 512; i += 256) {
        int k = i >> 3, q = i & 7;
        float4 v = (q < 4) ? ((const float4*)Wmu)[k * 4 + q]
                           : ((const float4*)Wls)[k * 4 + (q - 4)];
        ((float4*)&sW2[k][q])[0] = v;
    }
    if (t < 64) sWb[t] = make_float4(W1[t], W1[64 + t], b1[t], 0.0f);
    __syncthreads();

    int part = t & 3;               // which 8 of the 32 outputs
    int u    = t >> 2;              // 0..63
    int base = blockIdx.x * 256;

    float a0[4], a1[4], dd[4];
    #pragma unroll
    for (int i = 0; i < 4; i++) {
        int n = base + u + 64 * i;
        int nc = (n < N_NODES) ? n : 0;
        float d = rsqrtf(1.0f + g_deg[nc]);
        float2 xv = ((const float2*)x)[nc];
        float2 av = ((const float2*)g_acc0)[nc];
        a0[i] = d * av.x + d * d * xv.x;
        a1[i] = d * av.y + d * d * xv.y;
        dd[i] = d;
    }

    unsigned long long acc2[4][4];
    #pragma unroll
    for (int i = 0; i < 4; i++)
        #pragma unroll
        for (int j = 0; j < 4; j++) acc2[i][j] = 0ull;

    int q0 = part * 2;
    #pragma unroll 4
    for (int k = 0; k < 64; k++) {
        float4 wb = sWb[k];
        ulonglong2 wA = sW2[k][q0];       // outputs j.. j+3 (2 f32x2)
        ulonglong2 wB = sW2[k][q0 + 1];   // outputs j+4..j+7
        #pragma unroll
        for (int i = 0; i < 4; i++) {
            float hk = fmaxf(0.0f, fmaf(a0[i], wb.x, fmaf(a1[i], wb.y, wb.z)));
            unsigned long long hk2;
            PACK2(hk2, hk);
            FMA_F32X2(acc2[i][0], hk2, wA.x);
            FMA_F32X2(acc2[i][1], hk2, wA.y);
            FMA_F32X2(acc2[i][2], hk2, wB.x);
            FMA_F32X2(acc2[i][3], hk2, wB.y);
        }
    }

    #pragma unroll
    for (int i = 0; i < 4; i++) {
        int n = base + u + 64 * i;
        if (n < N_NODES) {
            float r[8];
            UNPACK2(r[0], r[1], acc2[i][0]);
            UNPACK2(r[2], r[3], acc2[i][1]);
            UNPACK2(r[4], r[5], acc2[i][2]);
            UNPACK2(r[6], r[7], acc2[i][3]);
            float4 vA = make_float4(dd[i] * r[0], dd[i] * r[1],
                                    dd[i] * r[2], dd[i] * r[3]);
            float4 vB = make_float4(dd[i] * r[4], dd[i] * r[5],
                                    dd[i] * r[6], dd[i] * r[7]);
            float4* gout = (float4*)(g_gvec + n * HMW + part * 8);
            float4* aout = (float4*)(g_acc1 + n * HMW + part * 8);
            gout[0] = vA; gout[1] = vB;
            aout[0] = vA; aout[1] = vB;     // self-loop seed (replaces zeroing)
        }
    }
}

// ---------------- layer-2 scatter: acc1[dst][:] += g[src][:]  (32 feats) --------
// 8 threads per edge; each does one float4 gather + one independent red.v4
__global__ void k_scatter1() {
    long long tid = (long long)blockIdx.x * 256 + threadIdx.x;
    if (tid >= (long long)N_EDGES * 8) return;
    int e = (int)(tid >> 3), q = (int)(tid & 7);
    int src = g_src32[e];
    int dst = g_dst32[e];
    float4 v = ((const float4*)g_gvec)[src * 8 + q];
    red_add_v4(&g_acc1[dst * HMW + q * 4], v);
}

// ---------------- epilogue: out = dis*acc1 + bias; split mu / logstd ------------
__global__ void k_out(const float* __restrict__ bmu, const float* __restrict__ bls,
                      float* __restrict__ out) {
    int tid = blockIdx.x * 256 + threadIdx.x;       // over N_NODES * 8 float4s
    if (tid >= N_NODES * 8) return;
    int n = tid >> 3, q = tid & 7;
    float d = rsqrtf(1.0f + g_deg[n]);
    float4 a = ((const float4*)g_acc1)[tid];
    float4 b = (q < 4) ? ((const float4*)bmu)[q] : ((const float4*)bls)[q - 4];
    float4 v = make_float4(fmaf(d, a.x, b.x), fmaf(d, a.y, b.y),
                           fmaf(d, a.z, b.z), fmaf(d, a.w, b.w));
    float* dst = (q < 4) ? out + n * OUTC + q * 4
                         : out + N_NODES * OUTC + n * OUTC + (q - 4) * 4;
    *(float4*)dst = v;
}

extern "C" void kernel_launch(void* const* d_in, const int* in_sizes, int n_in,
                              void* d_out, int out_size) {
    const float* x    = (const float*)d_in[0];
    const void*  ei   = d_in[1];                 // int32 or int64, detected on device
    const float* W1   = (const float*)d_in[2];
    const float* b1   = (const float*)d_in[3];
    const float* Wmu  = (const float*)d_in[4];
    const float* bmu  = (const float*)d_in[5];
    const float* Wls  = (const float*)d_in[6];
    const float* bls  = (const float*)d_in[7];
    float* out = (float*)d_out;

    const int IB  = (N_NODES * 2 / 4 + 255) / 256;        // 196
    const int EB  = (N_EDGES + 255) / 256;                // 6250
    const int HB  = (N_NODES + 255) / 256;                // 391
    const int OB  = (N_NODES * 8 + 255) / 256;            // 3125
    const int S1B = (int)(((long long)N_EDGES * 8 + 255) / 256);  // 50000

    k_init<<<IB, 256>>>((const unsigned*)ei);
    k_deg<<<EB, 256>>>(ei);
    k_scatter0<<<EB, 256>>>(x);
    k_hidden2<<<HB, 256>>>(x, W1, b1, Wmu, Wls);
    k_scatter1<<<S1B, 256>>>();
    k_out<<<OB, 256>>>(bmu, bls, out);
}